// round 2
// baseline (speedup 1.0000x reference)
#include <cuda_runtime.h>
#include <math.h>
#include <float.h>

#define BB 32
#define UUU 1024
#define MMM 65536

// output offsets (floats)
#define R_OFF   ((size_t)0)
#define H_OFF   ((size_t)32768)
#define C_OFF   ((size_t)65536)
#define MEM_OFF ((size_t)98304)
#define WU_OFF  ((size_t)67207168)
#define WLU_OFF ((size_t)69304320)
#define WR_OFF  ((size_t)71401472)

// ---------------- scratch (device globals, no allocation) ----------------
__device__ float g_zp[4 * 32 * 5120];        // gate GEMM k-split partials
__device__ float g_h[BB * UUU];              // h (post-activation)
__device__ float g_hss[128];                 // partial sums of h^2
__device__ float g_hinv[BB];                 // 1/||h||
__device__ float g_wwT[(size_t)MMM * BB];    // ww transposed [m][b]
__device__ float g_pm[512], g_ps[512];       // softmax partials
__device__ float g_gmax[BB], g_invden[BB];
__device__ float g_bv1[1024], g_bv2[1024], g_bmv[1024];
__device__ int   g_bmi[1024];
__device__ float g_nth[BB];
__device__ int   g_si[1];
__device__ float g_rp[(size_t)128 * BB * UUU]; // r split-K partials

__device__ __forceinline__ float hsig(float v) {
    return fminf(fmaxf(0.2f * v + 0.5f, 0.0f), 1.0f);
}

// ---------------- K1: gate GEMMs (x@W + h@R1 fused; r@R2), k-split 4 ----------------
// grid 160 = 40 j-tiles (128 cols) x 4 k-slices (256 k). block 256 threads, 4b x 4j per thread.
__global__ __launch_bounds__(256) void k_gemm(
    const float* __restrict__ x, const float* __restrict__ h,
    const float* __restrict__ r, const float* __restrict__ W,
    const float* __restrict__ RK, const float* __restrict__ bias)
{
    __shared__ float A_s[32][33];
    __shared__ float W_s[32][132];
    int jb = blockIdx.x >> 2;
    int ks = blockIdx.x & 3;
    int t = threadIdx.x;
    int b0 = (t >> 5) * 4;
    int j0 = (t & 31) * 4;
    int jbase = jb * 128;

    float acc[4][4];
#pragma unroll
    for (int i = 0; i < 4; i++)
#pragma unroll
        for (int j = 0; j < 4; j++) acc[i][j] = 0.0f;

    int nsrc = (jb < 32) ? 2 : 1;
    int kbase = ks * 256;
    for (int s = 0; s < nsrc; s++) {
        const float* A; const float* Wm; int ldw;
        if (jb < 32) {
            if (s == 0) { A = x; Wm = W;  ldw = 4096; }
            else        { A = h; Wm = RK; ldw = 5120; }
        } else          { A = r; Wm = RK; ldw = 5120; }

        for (int kc = 0; kc < 256; kc += 32) {
#pragma unroll
            for (int i = 0; i < 4; i++) {
                int e = t + i * 256;
                A_s[e >> 5][e & 31] = A[(e >> 5) * 1024 + kbase + kc + (e & 31)];
            }
#pragma unroll
            for (int i = 0; i < 16; i++) {
                int e = t + i * 256;
                int kk = e >> 7, j = e & 127;
                W_s[kk][j] = Wm[(size_t)(kbase + kc + kk) * ldw + jbase + j];
            }
            __syncthreads();
#pragma unroll
            for (int kk = 0; kk < 32; kk++) {
                float a0 = A_s[b0][kk], a1 = A_s[b0 + 1][kk];
                float a2 = A_s[b0 + 2][kk], a3 = A_s[b0 + 3][kk];
                float w0 = W_s[kk][j0], w1 = W_s[kk][j0 + 1];
                float w2 = W_s[kk][j0 + 2], w3 = W_s[kk][j0 + 3];
                acc[0][0] += a0 * w0; acc[0][1] += a0 * w1; acc[0][2] += a0 * w2; acc[0][3] += a0 * w3;
                acc[1][0] += a1 * w0; acc[1][1] += a1 * w1; acc[1][2] += a1 * w2; acc[1][3] += a1 * w3;
                acc[2][0] += a2 * w0; acc[2][1] += a2 * w1; acc[2][2] += a2 * w2; acc[2][3] += a2 * w3;
                acc[3][0] += a3 * w0; acc[3][1] += a3 * w1; acc[3][2] += a3 * w2; acc[3][3] += a3 * w3;
            }
            __syncthreads();
        }
    }
#pragma unroll
    for (int i = 0; i < 4; i++)
#pragma unroll
        for (int jj = 0; jj < 4; jj++) {
            int j = jbase + j0 + jj;
            float v = acc[i][jj];
            if (ks == 0 && jb < 32) v += bias[j];
            g_zp[((ks * 32) + (b0 + i)) * 5120 + j] = v;
        }
}

// ---------------- K2: reduce partials, activations, h, c, h^2 partials ----------------
__global__ __launch_bounds__(256) void k_gates(const float* __restrict__ c_tm1,
                                               float* __restrict__ out)
{
    int blk = blockIdx.x;            // 128
    int b = blk >> 2, uc = blk & 3;
    int u = uc * 256 + threadIdx.x;
    float zi = 0, zf = 0, zc = 0, zo = 0, ri = 0;
#pragma unroll
    for (int s = 0; s < 4; s++) {
        const float* p = &g_zp[(s * 32 + b) * 5120];
        zi += p[u]; zf += p[1024 + u]; zc += p[2048 + u]; zo += p[3072 + u]; ri += p[4096 + u];
    }
    float ig = hsig(zi + ri), fg = hsig(zf), og = hsig(zo);
    float c = fg * c_tm1[b * 1024 + u] + ig * tanhf(zc);
    float hh = og * tanhf(c);
    out[C_OFF + b * 1024 + u] = c;
    out[H_OFF + b * 1024 + u] = hh;
    g_h[b * 1024 + u] = hh;

    __shared__ float red[256];
    red[threadIdx.x] = hh * hh;
    __syncthreads();
    for (int s = 128; s > 0; s >>= 1) {
        if (threadIdx.x < s) red[threadIdx.x] += red[threadIdx.x + s];
        __syncthreads();
    }
    if (threadIdx.x == 0) g_hss[blk] = red[0];
}

__global__ void k_hinv() {
    int b = threadIdx.x;
    if (b < 32) {
        float s = g_hss[b * 4] + g_hss[b * 4 + 1] + g_hss[b * 4 + 2] + g_hss[b * 4 + 3];
        g_hinv[b] = rsqrtf(fmaxf(s, 1e-12f));
    }
}

// ---------------- K3: ww blend + transpose -> wwT[m][b] ----------------
__global__ __launch_bounds__(256) void k_ww(const float* __restrict__ wr_prev,
                                            const float* __restrict__ wlu,
                                            const float* __restrict__ wg)
{
    float sg = 1.0f / (1.0f + expf(-wg[0]));
    __shared__ float tile[32][33];
    int m0 = blockIdx.x * 32;
    int t = threadIdx.x;
    int cm = t & 31, r0 = t >> 5;
#pragma unroll
    for (int i = 0; i < 4; i++) {
        int b = r0 + i * 8;
        size_t idx = (size_t)b * 65536 + m0 + cm;
        tile[b][cm] = sg * wr_prev[idx] + (1.0f - sg) * wlu[idx];
    }
    __syncthreads();
    int b2 = t & 31;
#pragma unroll
    for (int i = 0; i < 4; i++) {
        int ml = (t >> 5) + i * 8;
        g_wwT[(size_t)(m0 + ml) * 32 + b2] = tile[b2][ml];
    }
}

// ---------------- K4: fused membank pass: sim raw dots, row ss, mem_new ----------------
// grid 1024 blocks (64 m each), 256 threads.
__global__ __launch_bounds__(256) void k_sim_mem(const float* __restrict__ mb,
                                                 float* __restrict__ out)
{
    __shared__ float h_s[32][65];
    __shared__ float mb_s[64][65];
    __shared__ float ww_s[64][32];
    __shared__ float ss_s[64];
    int m0 = blockIdx.x * 64;
    int t = threadIdx.x;

#pragma unroll
    for (int i = 0; i < 8; i++) {
        int e = t + i * 256;
        ww_s[e >> 5][e & 31] = g_wwT[(size_t)(m0 + (e >> 5)) * 32 + (e & 31)];
    }

    int bg = t & 7, mg = t >> 3;    // dots: 4b x 2m ; memnew: 8u x 2m (same split)
    int b0 = bg * 4, ml0 = mg * 2;
    int tu = t & 7;

    float dot[4][2] = {{0,0},{0,0},{0,0},{0,0}};
    float ss0 = 0.0f, ss1 = 0.0f;

    for (int uc = 0; uc < 1024; uc += 64) {
#pragma unroll
        for (int i = 0; i < 2; i++) {
            int e = t + i * 256;       // 512 float4
            int b = e >> 4, q = e & 15;
            float4 v = *(const float4*)&g_h[b * 1024 + uc + q * 4];
            h_s[b][q * 4 + 0] = v.x; h_s[b][q * 4 + 1] = v.y;
            h_s[b][q * 4 + 2] = v.z; h_s[b][q * 4 + 3] = v.w;
        }
#pragma unroll
        for (int i = 0; i < 4; i++) {
            int e = t + i * 256;       // 1024 float4
            int ml = e >> 4, q = e & 15;
            float4 v = *(const float4*)&mb[(size_t)(m0 + ml) * 1024 + uc + q * 4];
            mb_s[ml][q * 4 + 0] = v.x; mb_s[ml][q * 4 + 1] = v.y;
            mb_s[ml][q * 4 + 2] = v.z; mb_s[ml][q * 4 + 3] = v.w;
        }
        __syncthreads();

        // dot accumulation
#pragma unroll 4
        for (int uu = 0; uu < 64; uu++) {
            float m0v = mb_s[ml0][uu], m1v = mb_s[ml0 + 1][uu];
            float a0 = h_s[b0][uu], a1 = h_s[b0 + 1][uu];
            float a2 = h_s[b0 + 2][uu], a3 = h_s[b0 + 3][uu];
            dot[0][0] += a0 * m0v; dot[0][1] += a0 * m1v;
            dot[1][0] += a1 * m0v; dot[1][1] += a1 * m1v;
            dot[2][0] += a2 * m0v; dot[2][1] += a2 * m1v;
            dot[3][0] += a3 * m0v; dot[3][1] += a3 * m1v;
            if (bg == 0) { ss0 += m0v * m0v; ss1 += m1v * m1v; }
        }

        // mem_new for this u-chunk: rows ml0, ml0+1, u_sub = tu*8
        float acc0[8], acc1[8];
#pragma unroll
        for (int k = 0; k < 8; k++) {
            acc0[k] = mb_s[ml0][tu * 8 + k];
            acc1[k] = mb_s[ml0 + 1][tu * 8 + k];
        }
#pragma unroll 4
        for (int b = 0; b < 32; b++) {
            float w0 = ww_s[ml0][b], w1 = ww_s[ml0 + 1][b];
#pragma unroll
            for (int k = 0; k < 8; k++) {
                float hv = h_s[b][tu * 8 + k];
                acc0[k] += w0 * hv;
                acc1[k] += w1 * hv;
            }
        }
        size_t base0 = MEM_OFF + (size_t)(m0 + ml0) * 1024 + uc + tu * 8;
        size_t base1 = base0 + 1024;
        *(float4*)&out[base0]     = make_float4(acc0[0], acc0[1], acc0[2], acc0[3]);
        *(float4*)&out[base0 + 4] = make_float4(acc0[4], acc0[5], acc0[6], acc0[7]);
        *(float4*)&out[base1]     = make_float4(acc1[0], acc1[1], acc1[2], acc1[3]);
        *(float4*)&out[base1 + 4] = make_float4(acc1[4], acc1[5], acc1[6], acc1[7]);
        __syncthreads();
    }

    if (bg == 0) { ss_s[ml0] = ss0; ss_s[ml0 + 1] = ss1; }
    __syncthreads();

#pragma unroll
    for (int mi = 0; mi < 2; mi++) {
        float inv_m = rsqrtf(fmaxf(ss_s[ml0 + mi], 1e-12f));
#pragma unroll
        for (int bi = 0; bi < 4; bi++) {
            int b = b0 + bi;
            out[WR_OFF + (size_t)b * 65536 + m0 + ml0 + mi] = dot[bi][mi] * g_hinv[b] * inv_m;
        }
    }
}

// ---------------- K5: softmax partial reductions ----------------
__global__ __launch_bounds__(256) void k_red1(const float* __restrict__ outr)
{
    int blk = blockIdx.x;             // 512 = 32 b x 16 partitions
    int b = blk >> 4, p = blk & 15;
    const float* s = outr + WR_OFF + (size_t)b * 65536 + p * 4096;
    int t = threadIdx.x;
    float mx = -FLT_MAX;
    for (int k = 0; k < 16; k++) mx = fmaxf(mx, s[k * 256 + t]);
    __shared__ float red[256];
    red[t] = mx; __syncthreads();
    for (int st = 128; st > 0; st >>= 1) {
        if (t < st) red[t] = fmaxf(red[t], red[t + st]);
        __syncthreads();
    }
    float bmax = red[0];
    __syncthreads();
    float sum = 0;
    for (int k = 0; k < 16; k++) sum += expf(s[k * 256 + t] - bmax);
    red[t] = sum; __syncthreads();
    for (int st = 128; st > 0; st >>= 1) {
        if (t < st) red[t] += red[t + st];
        __syncthreads();
    }
    if (t == 0) { g_pm[blk] = bmax; g_ps[blk] = red[0]; }
}

__global__ void k_red2()
{
    int b = threadIdx.x;
    if (b >= 32) return;
    float gm = -FLT_MAX;
    for (int p = 0; p < 16; p++) gm = fmaxf(gm, g_pm[b * 16 + p]);
    float den = 0;
    for (int p = 0; p < 16; p++) den += g_ps[b * 16 + p] * expf(g_pm[b * 16 + p] - gm);
    g_gmax[b] = gm;
    g_invden[b] = 1.0f / den;
}

// ---------------- K6: wr (in place over sim), wu_new, order-stat partials ----------------
__global__ __launch_bounds__(256) void k_wr_wu(const float* __restrict__ wu,
                                               const float* __restrict__ wlu,
                                               const float* __restrict__ wr_prev,
                                               const float* __restrict__ wg,
                                               float* __restrict__ out)
{
    int blk = blockIdx.x;             // 1024 = 32 b x 32 chunks
    int b = blk >> 5, mc = blk & 31;
    int t = threadIdx.x;
    size_t base = (size_t)b * 65536 + (size_t)mc * 2048 + (size_t)t * 8;
    float sg = 1.0f / (1.0f + expf(-wg[0]));
    float gm = g_gmax[b], inv = g_invden[b];

    float s1 = FLT_MAX, s2 = FLT_MAX;
    float mv = FLT_MAX; int mi_ = 0x7fffffff;
#pragma unroll
    for (int k = 0; k < 8; k++) {
        size_t idx = base + k;
        float sim = out[WR_OFF + idx];
        float wr = expf(sim - gm) * inv;
        out[WR_OFF + idx] = wr;
        float ww = sg * wr_prev[idx] + (1.0f - sg) * wlu[idx];
        float wun = 0.5f * wu[idx] + wr + ww;
        out[WU_OFF + idx] = wun;
        if (wun < s1) { s2 = s1; s1 = wun; }
        else if (wun < s2) { s2 = wun; }
        int m = (int)(idx - (size_t)b * 65536);
        if (wun < mv || (wun == mv && m < mi_)) { mv = wun; mi_ = m; }
    }
    __shared__ float r1[256], r2[256], rv[256];
    __shared__ int ri_[256];
    r1[t] = s1; r2[t] = s2; rv[t] = mv; ri_[t] = mi_;
    __syncthreads();
    for (int st = 128; st > 0; st >>= 1) {
        if (t < st) {
            float b1 = r1[t + st], b2 = r2[t + st];
            float a1 = r1[t], a2 = r2[t];
            if (b1 < a1) { a2 = fminf(a1, b2); a1 = b1; }
            else         { a2 = fminf(a2, b1); }
            r1[t] = a1; r2[t] = a2;
            float bv = rv[t + st]; int bi2 = ri_[t + st];
            if (bv < rv[t] || (bv == rv[t] && bi2 < ri_[t])) { rv[t] = bv; ri_[t] = bi2; }
        }
        __syncthreads();
    }
    if (t == 0) { g_bv1[blk] = r1[0]; g_bv2[blk] = r2[0]; g_bmv[blk] = rv[0]; g_bmi[blk] = ri_[0]; }
}

__global__ void k_redmin()
{
    int b = threadIdx.x;
    __shared__ int sidx[32];
    if (b < 32) {
        float s1 = FLT_MAX, s2 = FLT_MAX;
        float mv = FLT_MAX; int mi_ = 0x7fffffff;
        for (int p = 0; p < 32; p++) {
            int blk = b * 32 + p;
            float b1 = g_bv1[blk], b2 = g_bv2[blk];
            if (b1 < s1) { s2 = fminf(s1, b2); s1 = b1; }
            else         { s2 = fminf(s2, b1); }
            float bv = g_bmv[blk]; int bi2 = g_bmi[blk];
            if (bv < mv || (bv == mv && bi2 < mi_)) { mv = bv; mi_ = bi2; }
        }
        g_nth[b] = s2;
        sidx[b] = mi_;
    }
    __syncthreads();
    if (b == 0) {
        int m = sidx[0];
        for (int i = 1; i < 32; i++) m = min(m, sidx[i]);
        g_si[0] = m;
    }
}

// ---------------- K7: wlu_new ----------------
__global__ __launch_bounds__(256) void k_wlu(float* __restrict__ out)
{
    int blk = blockIdx.x;
    int b = blk >> 5, mc = blk & 31;
    size_t base = (size_t)b * 65536 + (size_t)mc * 2048 + (size_t)threadIdx.x * 8;
    float nth = g_nth[b];
#pragma unroll
    for (int k = 0; k < 8; k++)
        out[WLU_OFF + base + k] = (out[WU_OFF + base + k] <= nth) ? 1.0f : 0.0f;
}

// ---------------- K8: keep-row fixup on mem_new ----------------
__global__ void k_fixrow(const float* __restrict__ mb, float* __restrict__ out)
{
    int m = g_si[0];
    for (int u = threadIdx.x; u < 1024; u += blockDim.x)
        out[MEM_OFF + (size_t)m * 1024 + u] -= mb[(size_t)m * 1024 + u];
}

// ---------------- K9: r = wr @ membank (split-K) ----------------
__global__ __launch_bounds__(256) void k_r(const float* __restrict__ mb,
                                           const float* __restrict__ out)
{
    __shared__ float wr_s[32][65];
    int blk = blockIdx.x;            // 512 = 128 k-slices x 4 u-tiles
    int slice = blk >> 2;
    int ut = blk & 3;
    int t = threadIdx.x;
    int tu = t & 63, bgp = t >> 6;
    int b0 = bgp * 8;
    int u = ut * 256 + tu * 4;
    int mbase = slice * 512;

    float acc[8][4];
#pragma unroll
    for (int i = 0; i < 8; i++)
#pragma unroll
        for (int j = 0; j < 4; j++) acc[i][j] = 0.0f;

    for (int mc = 0; mc < 512; mc += 64) {
#pragma unroll
        for (int i = 0; i < 8; i++) {
            int e = t + i * 256;
            wr_s[e >> 6][e & 63] = out[WR_OFF + (size_t)(e >> 6) * 65536 + mbase + mc + (e & 63)];
        }
        __syncthreads();
#pragma unroll 2
        for (int mm = 0; mm < 64; mm++) {
            float4 v = *(const float4*)&mb[(size_t)(mbase + mc + mm) * 1024 + u];
#pragma unroll
            for (int bi = 0; bi < 8; bi++) {
                float w = wr_s[b0 + bi][mm];
                acc[bi][0] += w * v.x; acc[bi][1] += w * v.y;
                acc[bi][2] += w * v.z; acc[bi][3] += w * v.w;
            }
        }
        __syncthreads();
    }
#pragma unroll
    for (int bi = 0; bi < 8; bi++)
        *(float4*)&g_rp[((size_t)slice * 32 + b0 + bi) * 1024 + u] =
            make_float4(acc[bi][0], acc[bi][1], acc[bi][2], acc[bi][3]);
}

__global__ __launch_bounds__(256) void k_rred(float* __restrict__ out)
{
    int idx = blockIdx.x * 256 + threadIdx.x;   // 0..32767
    float s = 0;
    for (int sl = 0; sl < 128; sl++) s += g_rp[(size_t)sl * 32768 + idx];
    out[R_OFF + idx] = s;
}

// ---------------- launcher ----------------
extern "C" void kernel_launch(void* const* d_in, const int* in_sizes, int n_in,
                              void* d_out, int out_size)
{
    const float* x        = (const float*)d_in[0];
    const float* h_tm1    = (const float*)d_in[1];
    const float* c_tm1    = (const float*)d_in[2];
    const float* r_tm1    = (const float*)d_in[3];
    const float* membank  = (const float*)d_in[4];
    const float* wu       = (const float*)d_in[5];
    const float* wlu      = (const float*)d_in[6];
    const float* wr_prev  = (const float*)d_in[7];
    const float* Wk       = (const float*)d_in[8];
    const float* RK       = (const float*)d_in[9];
    const float* bias     = (const float*)d_in[10];
    const float* wgate    = (const float*)d_in[11];
    float* out = (float*)d_out;

    k_gemm<<<160, 256>>>(x, h_tm1, r_tm1, Wk, RK, bias);
    k_gates<<<128, 256>>>(c_tm1, out);
    k_hinv<<<1, 32>>>();
    k_ww<<<2048, 256>>>(wr_prev, wlu, wgate);
    k_sim_mem<<<1024, 256>>>(membank, out);
    k_red1<<<512, 256>>>(out);
    k_red2<<<1, 32>>>();
    k_wr_wu<<<1024, 256>>>(wu, wlu, wr_prev, wgate, out);
    k_redmin<<<1, 32>>>();
    k_wlu<<<1024, 256>>>(out);
    k_fixrow<<<1, 256>>>(membank, out);
    k_r<<<512, 256>>>(membank, out);
    k_rred<<<128, 256>>>(out);
}

// round 3
// speedup vs baseline: 1.1480x; 1.1480x over previous
#include <cuda_runtime.h>
#include <math.h>
#include <float.h>

#define BB 32
#define UUU 1024
#define MMM 65536

// output offsets (floats)
#define R_OFF   ((size_t)0)
#define H_OFF   ((size_t)32768)
#define C_OFF   ((size_t)65536)
#define MEM_OFF ((size_t)98304)
#define WU_OFF  ((size_t)67207168)
#define WLU_OFF ((size_t)69304320)
#define WR_OFF  ((size_t)71401472)

typedef unsigned long long ull;

__device__ __forceinline__ ull fpk(float x, float y) {
    ull r; asm("mov.b64 %0, {%1,%2};" : "=l"(r) : "f"(x), "f"(y)); return r;
}
__device__ __forceinline__ ull fdup(float x) {
    ull r; asm("mov.b64 %0, {%1,%1};" : "=l"(r) : "f"(x)); return r;
}
__device__ __forceinline__ void ffma2(ull &d, ull a, ull b) {
    asm("fma.rn.f32x2 %0, %1, %2, %0;" : "+l"(d) : "l"(a), "l"(b));
}
__device__ __forceinline__ float2 fupk(ull v) {
    float2 f; asm("mov.b64 {%0,%1}, %2;" : "=f"(f.x), "=f"(f.y) : "l"(v)); return f;
}

// ---------------- scratch (device globals, no allocation) ----------------
__device__ float g_zp[4 * 32 * 5120];        // gate GEMM k-split partials
__device__ float g_h[BB * UUU];              // h (post-activation)
__device__ float g_hss[128];                 // partial sums of h^2
__device__ float g_hinv[BB];                 // 1/||h||
__device__ float g_pm[512], g_ps[512];       // softmax partials
__device__ float g_gmax[BB], g_invden[BB];
__device__ float g_bv1[1024], g_bv2[1024], g_bmv[1024];
__device__ int   g_bmi[1024];
__device__ float g_nth[BB];
__device__ int   g_si[1];
__device__ float g_rp[(size_t)128 * BB * UUU]; // r split-K partials

__device__ __forceinline__ float hsig(float v) {
    return fminf(fmaxf(0.2f * v + 0.5f, 0.0f), 1.0f);
}

// ---------------- K1: gate GEMMs (x@W + h@R1 fused; r@R2), k-split 4 ----------------
__global__ __launch_bounds__(256) void k_gemm(
    const float* __restrict__ x, const float* __restrict__ h,
    const float* __restrict__ r, const float* __restrict__ W,
    const float* __restrict__ RK, const float* __restrict__ bias)
{
    __shared__ float A_s[32][33];
    __shared__ __align__(16) float W_s[32][132];
    int jb = blockIdx.x >> 2;
    int ks = blockIdx.x & 3;
    int t = threadIdx.x;
    int b0 = (t >> 5) * 4;
    int j0 = (t & 31) * 4;
    int jbase = jb * 128;

    ull accp[4][2];
#pragma unroll
    for (int i = 0; i < 4; i++) { accp[i][0] = 0ULL; accp[i][1] = 0ULL; }

    int nsrc = (jb < 32) ? 2 : 1;
    int kbase = ks * 256;
    for (int s = 0; s < nsrc; s++) {
        const float* A; const float* Wm; int ldw;
        if (jb < 32) {
            if (s == 0) { A = x; Wm = W;  ldw = 4096; }
            else        { A = h; Wm = RK; ldw = 5120; }
        } else          { A = r; Wm = RK; ldw = 5120; }

        for (int kc = 0; kc < 256; kc += 32) {
#pragma unroll
            for (int i = 0; i < 4; i++) {
                int e = t + i * 256;
                A_s[e >> 5][e & 31] = A[(e >> 5) * 1024 + kbase + kc + (e & 31)];
            }
#pragma unroll
            for (int i = 0; i < 16; i++) {
                int e = t + i * 256;
                int kk = e >> 7, j = e & 127;
                W_s[kk][j] = Wm[(size_t)(kbase + kc + kk) * ldw + jbase + j];
            }
            __syncthreads();
#pragma unroll
            for (int kk = 0; kk < 32; kk++) {
                ull wp0 = *(const ull*)&W_s[kk][j0];
                ull wp1 = *(const ull*)&W_s[kk][j0 + 2];
#pragma unroll
                for (int i = 0; i < 4; i++) {
                    ull ad = fdup(A_s[b0 + i][kk]);
                    ffma2(accp[i][0], ad, wp0);
                    ffma2(accp[i][1], ad, wp1);
                }
            }
            __syncthreads();
        }
    }
#pragma unroll
    for (int i = 0; i < 4; i++) {
#pragma unroll
        for (int jp = 0; jp < 2; jp++) {
            float2 f = fupk(accp[i][jp]);
            int j = jbase + j0 + jp * 2;
            float v0 = f.x, v1 = f.y;
            if (ks == 0 && jb < 32) { v0 += bias[j]; v1 += bias[j + 1]; }
            g_zp[((ks * 32) + (b0 + i)) * 5120 + j]     = v0;
            g_zp[((ks * 32) + (b0 + i)) * 5120 + j + 1] = v1;
        }
    }
}

// ---------------- K2: reduce partials, activations, h, c, h^2 partials ----------------
__global__ __launch_bounds__(256) void k_gates(const float* __restrict__ c_tm1,
                                               float* __restrict__ out)
{
    int blk = blockIdx.x;            // 128
    int b = blk >> 2, uc = blk & 3;
    int u = uc * 256 + threadIdx.x;
    float zi = 0, zf = 0, zc = 0, zo = 0, ri = 0;
#pragma unroll
    for (int s = 0; s < 4; s++) {
        const float* p = &g_zp[(s * 32 + b) * 5120];
        zi += p[u]; zf += p[1024 + u]; zc += p[2048 + u]; zo += p[3072 + u]; ri += p[4096 + u];
    }
    float ig = hsig(zi + ri), fg = hsig(zf), og = hsig(zo);
    float c = fg * c_tm1[b * 1024 + u] + ig * tanhf(zc);
    float hh = og * tanhf(c);
    out[C_OFF + b * 1024 + u] = c;
    out[H_OFF + b * 1024 + u] = hh;
    g_h[b * 1024 + u] = hh;

    __shared__ float red[256];
    red[threadIdx.x] = hh * hh;
    __syncthreads();
    for (int s = 128; s > 0; s >>= 1) {
        if (threadIdx.x < s) red[threadIdx.x] += red[threadIdx.x + s];
        __syncthreads();
    }
    if (threadIdx.x == 0) g_hss[blk] = red[0];
}

__global__ void k_hinv() {
    int b = threadIdx.x;
    if (b < 32) {
        float s = g_hss[b * 4] + g_hss[b * 4 + 1] + g_hss[b * 4 + 2] + g_hss[b * 4 + 3];
        g_hinv[b] = rsqrtf(fmaxf(s, 1e-12f));
    }
}

// ---------------- K4: fused membank pass: sim dots, row ss, mem_new, ww on the fly ----
// grid 1024 blocks (64 m each), 256 threads, f32x2-packed over u.
__global__ __launch_bounds__(256) void k_sim_mem(const float* __restrict__ mb,
                                                 const float* __restrict__ wr_prev,
                                                 const float* __restrict__ wlu,
                                                 const float* __restrict__ wg,
                                                 float* __restrict__ out)
{
    __shared__ __align__(16) float h_s[32][66];
    __shared__ __align__(16) float mb_s[64][66];
    __shared__ float ww_s[64][33];
    __shared__ float ss_s[64];
    int m0 = blockIdx.x * 64;
    int t = threadIdx.x;

    // ww tile: ww_s[ml][b]
    float sg = 1.0f / (1.0f + expf(-wg[0]));
#pragma unroll
    for (int i = 0; i < 8; i++) {
        int e = t + i * 256;
        int b = e >> 6, ml = e & 63;
        size_t gi = (size_t)b * 65536 + m0 + ml;
        ww_s[ml][b] = sg * wr_prev[gi] + (1.0f - sg) * wlu[gi];
    }

    // dot mapping: 2b x 4m per thread
    int bg = t & 15, mg = t >> 4;
    int b0 = bg * 2, ml0 = mg * 4;
    // memnew mapping: 2m x 8u per thread
    int ugn = t & 7, mgn = t >> 3;
    int mn0 = mgn * 2, un0 = ugn * 8;

    ull dotp[2][4];
    ull ssp[4];
#pragma unroll
    for (int j = 0; j < 4; j++) { dotp[0][j] = 0ULL; dotp[1][j] = 0ULL; ssp[j] = 0ULL; }

    for (int uc = 0; uc < 1024; uc += 64) {
#pragma unroll
        for (int i = 0; i < 4; i++) {
            int f = t + i * 256;
            int row = f >> 5, c2 = (f & 31) * 2;
            *(float2*)&h_s[row][c2] = *(const float2*)&g_h[row * 1024 + uc + c2];
        }
#pragma unroll
        for (int i = 0; i < 8; i++) {
            int f = t + i * 256;
            int row = f >> 5, c2 = (f & 31) * 2;
            *(float2*)&mb_s[row][c2] = *(const float2*)&mb[(size_t)(m0 + row) * 1024 + uc + c2];
        }
        __syncthreads();

        // dots (packed over u)
#pragma unroll 4
        for (int u2 = 0; u2 < 32; u2++) {
            ull hp0 = *(const ull*)&h_s[b0][u2 * 2];
            ull hp1 = *(const ull*)&h_s[b0 + 1][u2 * 2];
            ull mp0 = *(const ull*)&mb_s[ml0][u2 * 2];
            ull mp1 = *(const ull*)&mb_s[ml0 + 1][u2 * 2];
            ull mp2 = *(const ull*)&mb_s[ml0 + 2][u2 * 2];
            ull mp3 = *(const ull*)&mb_s[ml0 + 3][u2 * 2];
            ffma2(dotp[0][0], hp0, mp0); ffma2(dotp[0][1], hp0, mp1);
            ffma2(dotp[0][2], hp0, mp2); ffma2(dotp[0][3], hp0, mp3);
            ffma2(dotp[1][0], hp1, mp0); ffma2(dotp[1][1], hp1, mp1);
            ffma2(dotp[1][2], hp1, mp2); ffma2(dotp[1][3], hp1, mp3);
            if (bg == 0) {
                ffma2(ssp[0], mp0, mp0); ffma2(ssp[1], mp1, mp1);
                ffma2(ssp[2], mp2, mp2); ffma2(ssp[3], mp3, mp3);
            }
        }

        // mem_new (packed over u): rows mn0, mn0+1, cols un0..un0+7
        ull a0[4], a1[4];
#pragma unroll
        for (int q = 0; q < 4; q++) {
            a0[q] = *(const ull*)&mb_s[mn0][un0 + q * 2];
            a1[q] = *(const ull*)&mb_s[mn0 + 1][un0 + q * 2];
        }
#pragma unroll 4
        for (int b = 0; b < 32; b++) {
            ull w0 = fdup(ww_s[mn0][b]);
            ull w1 = fdup(ww_s[mn0 + 1][b]);
#pragma unroll
            for (int q = 0; q < 4; q++) {
                ull hq = *(const ull*)&h_s[b][un0 + q * 2];
                ffma2(a0[q], w0, hq);
                ffma2(a1[q], w1, hq);
            }
        }
        size_t o0 = MEM_OFF + (size_t)(m0 + mn0) * 1024 + uc + un0;
#pragma unroll
        for (int q = 0; q < 4; q++) {
            *(ull*)&out[o0 + q * 2]        = a0[q];
            *(ull*)&out[o0 + 1024 + q * 2] = a1[q];
        }
        __syncthreads();
    }

    if (bg == 0) {
#pragma unroll
        for (int j = 0; j < 4; j++) {
            float2 f = fupk(ssp[j]);
            ss_s[ml0 + j] = f.x + f.y;
        }
    }
    __syncthreads();

#pragma unroll
    for (int j = 0; j < 4; j++) {
        float inv_m = rsqrtf(fmaxf(ss_s[ml0 + j], 1e-12f));
#pragma unroll
        for (int bi = 0; bi < 2; bi++) {
            float2 f = fupk(dotp[bi][j]);
            out[WR_OFF + (size_t)(b0 + bi) * 65536 + m0 + ml0 + j] =
                (f.x + f.y) * g_hinv[b0 + bi] * inv_m;
        }
    }
}

// ---------------- K5: softmax partial reductions ----------------
__global__ __launch_bounds__(256) void k_red1(const float* __restrict__ outr)
{
    int blk = blockIdx.x;             // 512 = 32 b x 16 partitions
    int b = blk >> 4, p = blk & 15;
    const float* s = outr + WR_OFF + (size_t)b * 65536 + p * 4096;
    int t = threadIdx.x;
    float mx = -FLT_MAX;
    for (int k = 0; k < 16; k++) mx = fmaxf(mx, s[k * 256 + t]);
    __shared__ float red[256];
    red[t] = mx; __syncthreads();
    for (int st = 128; st > 0; st >>= 1) {
        if (t < st) red[t] = fmaxf(red[t], red[t + st]);
        __syncthreads();
    }
    float bmax = red[0];
    __syncthreads();
    float sum = 0;
    for (int k = 0; k < 16; k++) sum += expf(s[k * 256 + t] - bmax);
    red[t] = sum; __syncthreads();
    for (int st = 128; st > 0; st >>= 1) {
        if (t < st) red[t] += red[t + st];
        __syncthreads();
    }
    if (t == 0) { g_pm[blk] = bmax; g_ps[blk] = red[0]; }
}

__global__ void k_red2()
{
    int b = threadIdx.x;
    if (b >= 32) return;
    float gm = -FLT_MAX;
    for (int p = 0; p < 16; p++) gm = fmaxf(gm, g_pm[b * 16 + p]);
    float den = 0;
    for (int p = 0; p < 16; p++) den += g_ps[b * 16 + p] * expf(g_pm[b * 16 + p] - gm);
    g_gmax[b] = gm;
    g_invden[b] = 1.0f / den;
}

// ---------------- K6: wr (in place over sim), wu_new, order-stat partials ----------------
__global__ __launch_bounds__(256) void k_wr_wu(const float* __restrict__ wu,
                                               const float* __restrict__ wlu,
                                               const float* __restrict__ wr_prev,
                                               const float* __restrict__ wg,
                                               float* __restrict__ out)
{
    int blk = blockIdx.x;             // 1024 = 32 b x 32 chunks
    int b = blk >> 5, mc = blk & 31;
    int t = threadIdx.x;
    size_t base = (size_t)b * 65536 + (size_t)mc * 2048 + (size_t)t * 8;
    float sg = 1.0f / (1.0f + expf(-wg[0]));
    float gm = g_gmax[b], inv = g_invden[b];

    float s1 = FLT_MAX, s2 = FLT_MAX;
    float mv = FLT_MAX; int mi_ = 0x7fffffff;
#pragma unroll
    for (int k = 0; k < 8; k++) {
        size_t idx = base + k;
        float sim = out[WR_OFF + idx];
        float wr = expf(sim - gm) * inv;
        out[WR_OFF + idx] = wr;
        float ww = sg * wr_prev[idx] + (1.0f - sg) * wlu[idx];
        float wun = 0.5f * wu[idx] + wr + ww;
        out[WU_OFF + idx] = wun;
        if (wun < s1) { s2 = s1; s1 = wun; }
        else if (wun < s2) { s2 = wun; }
        int m = (int)(idx - (size_t)b * 65536);
        if (wun < mv || (wun == mv && m < mi_)) { mv = wun; mi_ = m; }
    }
    __shared__ float r1[256], r2[256], rv[256];
    __shared__ int ri_[256];
    r1[t] = s1; r2[t] = s2; rv[t] = mv; ri_[t] = mi_;
    __syncthreads();
    for (int st = 128; st > 0; st >>= 1) {
        if (t < st) {
            float b1 = r1[t + st], b2 = r2[t + st];
            float a1 = r1[t], a2 = r2[t];
            if (b1 < a1) { a2 = fminf(a1, b2); a1 = b1; }
            else         { a2 = fminf(a2, b1); }
            r1[t] = a1; r2[t] = a2;
            float bv = rv[t + st]; int bi2 = ri_[t + st];
            if (bv < rv[t] || (bv == rv[t] && bi2 < ri_[t])) { rv[t] = bv; ri_[t] = bi2; }
        }
        __syncthreads();
    }
    if (t == 0) { g_bv1[blk] = r1[0]; g_bv2[blk] = r2[0]; g_bmv[blk] = rv[0]; g_bmi[blk] = ri_[0]; }
}

__global__ void k_redmin()
{
    int b = threadIdx.x;
    __shared__ int sidx[32];
    if (b < 32) {
        float s1 = FLT_MAX, s2 = FLT_MAX;
        float mv = FLT_MAX; int mi_ = 0x7fffffff;
        for (int p = 0; p < 32; p++) {
            int blk = b * 32 + p;
            float b1 = g_bv1[blk], b2 = g_bv2[blk];
            if (b1 < s1) { s2 = fminf(s1, b2); s1 = b1; }
            else         { s2 = fminf(s2, b1); }
            float bv = g_bmv[blk]; int bi2 = g_bmi[blk];
            if (bv < mv || (bv == mv && bi2 < mi_)) { mv = bv; mi_ = bi2; }
        }
        g_nth[b] = s2;
        sidx[b] = mi_;
    }
    __syncthreads();
    if (b == 0) {
        int m = sidx[0];
        for (int i = 1; i < 32; i++) m = min(m, sidx[i]);
        g_si[0] = m;
    }
}

// ---------------- K7: wlu_new ----------------
__global__ __launch_bounds__(256) void k_wlu(float* __restrict__ out)
{
    int blk = blockIdx.x;
    int b = blk >> 5, mc = blk & 31;
    size_t base = (size_t)b * 65536 + (size_t)mc * 2048 + (size_t)threadIdx.x * 8;
    float nth = g_nth[b];
#pragma unroll
    for (int k = 0; k < 8; k++)
        out[WLU_OFF + base + k] = (out[WU_OFF + base + k] <= nth) ? 1.0f : 0.0f;
}

// ---------------- K8: keep-row fixup on mem_new ----------------
__global__ void k_fixrow(const float* __restrict__ mb, float* __restrict__ out)
{
    int m = g_si[0];
    for (int u = threadIdx.x; u < 1024; u += blockDim.x)
        out[MEM_OFF + (size_t)m * 1024 + u] -= mb[(size_t)m * 1024 + u];
}

// ---------------- K9: r = wr @ membank (split-K), f32x2 packed over b-pairs -------------
__global__ __launch_bounds__(256) void k_r(const float* __restrict__ mb,
                                           const float* __restrict__ out)
{
    __shared__ __align__(16) float wr_t[64][34];
    int slice = blockIdx.x >> 2;
    int ut = blockIdx.x & 3;
    int t = threadIdx.x;
    int tu = t & 63;
    int b0 = (t >> 6) * 8;
    int u = ut * 256 + tu * 4;
    int mbase = slice * 512;

    ull accp[4][4];
#pragma unroll
    for (int i = 0; i < 4; i++)
#pragma unroll
        for (int j = 0; j < 4; j++) accp[i][j] = 0ULL;

    for (int mc = 0; mc < 512; mc += 64) {
#pragma unroll
        for (int i = 0; i < 8; i++) {
            int e = t + i * 256;
            int b = e >> 6, mm = e & 63;
            wr_t[mm][b] = out[WR_OFF + (size_t)b * 65536 + mbase + mc + mm];
        }
        __syncthreads();
#pragma unroll 8
        for (int mm = 0; mm < 64; mm++) {
            float4 v = *(const float4*)&mb[(size_t)(mbase + mc + mm) * 1024 + u];
            ull vd0 = fdup(v.x), vd1 = fdup(v.y), vd2 = fdup(v.z), vd3 = fdup(v.w);
#pragma unroll
            for (int bp = 0; bp < 4; bp++) {
                ull wp = *(const ull*)&wr_t[mm][b0 + bp * 2];
                ffma2(accp[bp][0], wp, vd0);
                ffma2(accp[bp][1], wp, vd1);
                ffma2(accp[bp][2], wp, vd2);
                ffma2(accp[bp][3], wp, vd3);
            }
        }
        __syncthreads();
    }
#pragma unroll
    for (int bp = 0; bp < 4; bp++) {
        float2 f0 = fupk(accp[bp][0]), f1 = fupk(accp[bp][1]);
        float2 f2 = fupk(accp[bp][2]), f3 = fupk(accp[bp][3]);
        size_t base = ((size_t)slice * 32 + b0 + bp * 2) * 1024 + u;
        *(float4*)&g_rp[base]        = make_float4(f0.x, f1.x, f2.x, f3.x);
        *(float4*)&g_rp[base + 1024] = make_float4(f0.y, f1.y, f2.y, f3.y);
    }
}

__global__ __launch_bounds__(256) void k_rred(float* __restrict__ out)
{
    int idx = blockIdx.x * 256 + threadIdx.x;   // 0..32767
    float s = 0;
    for (int sl = 0; sl < 128; sl++) s += g_rp[(size_t)sl * 32768 + idx];
    out[R_OFF + idx] = s;
}

// ---------------- launcher ----------------
extern "C" void kernel_launch(void* const* d_in, const int* in_sizes, int n_in,
                              void* d_out, int out_size)
{
    const float* x        = (const float*)d_in[0];
    const float* h_tm1    = (const float*)d_in[1];
    const float* c_tm1    = (const float*)d_in[2];
    const float* r_tm1    = (const float*)d_in[3];
    const float* membank  = (const float*)d_in[4];
    const float* wu       = (const float*)d_in[5];
    const float* wlu      = (const float*)d_in[6];
    const float* wr_prev  = (const float*)d_in[7];
    const float* Wk       = (const float*)d_in[8];
    const float* RK       = (const float*)d_in[9];
    const float* bias     = (const float*)d_in[10];
    const float* wgate    = (const float*)d_in[11];
    float* out = (float*)d_out;

    k_gemm<<<160, 256>>>(x, h_tm1, r_tm1, Wk, RK, bias);
    k_gates<<<128, 256>>>(c_tm1, out);
    k_hinv<<<1, 32>>>();
    k_sim_mem<<<1024, 256>>>(membank, wr_prev, wlu, wgate, out);
    k_red1<<<512, 256>>>(out);
    k_red2<<<1, 32>>>();
    k_wr_wu<<<1024, 256>>>(wu, wlu, wr_prev, wgate, out);
    k_redmin<<<1, 32>>>();
    k_wlu<<<1024, 256>>>(out);
    k_fixrow<<<1, 256>>>(membank, out);
    k_r<<<512, 256>>>(membank, out);
    k_rred<<<128, 256>>>(out);
}

// round 4
// speedup vs baseline: 1.5504x; 1.3505x over previous
#include <cuda_runtime.h>
#include <math.h>
#include <float.h>

#define BB 32
#define UUU 1024
#define MMM 65536

// output offsets (floats)
#define R_OFF   ((size_t)0)
#define H_OFF   ((size_t)32768)
#define C_OFF   ((size_t)65536)
#define MEM_OFF ((size_t)98304)
#define WU_OFF  ((size_t)67207168)
#define WLU_OFF ((size_t)69304320)
#define WR_OFF  ((size_t)71401472)

typedef unsigned long long ull;

__device__ __forceinline__ ull fdup(float x) {
    ull r; asm("mov.b64 %0, {%1,%1};" : "=l"(r) : "f"(x)); return r;
}
__device__ __forceinline__ void ffma2(ull &d, ull a, ull b) {
    asm("fma.rn.f32x2 %0, %1, %2, %0;" : "+l"(d) : "l"(a), "l"(b));
}
__device__ __forceinline__ float2 fupk(ull v) {
    float2 f; asm("mov.b64 {%0,%1}, %2;" : "=f"(f.x), "=f"(f.y) : "l"(v)); return f;
}

// ---------------- scratch (device globals, no allocation) ----------------
__device__ float g_zp[4 * 32 * 5120];        // gate GEMM k-split partials
__device__ float g_h[BB * UUU];              // h (post-activation)
__device__ float g_hss[128];                 // partial sums of h^2
__device__ float g_hinv[BB];                 // 1/||h||
__device__ float g_pm[512], g_ps[512];       // softmax partials
__device__ float g_gmax[BB], g_invden[BB];
__device__ float g_bv1[1024], g_bv2[1024], g_bmv[1024];
__device__ int   g_bmi[1024];
__device__ float g_nth[BB];
__device__ int   g_si[1];
__device__ float g_rp[(size_t)128 * BB * UUU]; // r split-K partials

__device__ __forceinline__ float hsig(float v) {
    return fminf(fmaxf(0.2f * v + 0.5f, 0.0f), 1.0f);
}

// ---------------- K1: gate GEMMs (x@W + h@R1 fused; r@R2), k-split 4 ----------------
__global__ __launch_bounds__(256) void k_gemm(
    const float* __restrict__ x, const float* __restrict__ h,
    const float* __restrict__ r, const float* __restrict__ W,
    const float* __restrict__ RK, const float* __restrict__ bias)
{
    __shared__ ull A2[32 * 34];                   // dup-packed A
    __shared__ __align__(16) float W_s[32][132];
    int jb = blockIdx.x >> 2;
    int ks = blockIdx.x & 3;
    int t = threadIdx.x;
    int b0 = (t >> 5) * 4;
    int j0 = (t & 31) * 4;
    int jbase = jb * 128;

    ull accp[4][2];
#pragma unroll
    for (int i = 0; i < 4; i++) { accp[i][0] = 0ULL; accp[i][1] = 0ULL; }

    int nsrc = (jb < 32) ? 2 : 1;
    int kbase = ks * 256;
    for (int s = 0; s < nsrc; s++) {
        const float* A; const float* Wm; int ldw;
        if (jb < 32) {
            if (s == 0) { A = x; Wm = W;  ldw = 4096; }
            else        { A = h; Wm = RK; ldw = 5120; }
        } else          { A = r; Wm = RK; ldw = 5120; }

        for (int kc = 0; kc < 256; kc += 32) {
#pragma unroll
            for (int i = 0; i < 4; i++) {
                int e = t + i * 256;
                A2[(e >> 5) * 34 + (e & 31)] =
                    fdup(A[(e >> 5) * 1024 + kbase + kc + (e & 31)]);
            }
#pragma unroll
            for (int i = 0; i < 16; i++) {
                int e = t + i * 256;
                int kk = e >> 7, j = e & 127;
                W_s[kk][j] = Wm[(size_t)(kbase + kc + kk) * ldw + jbase + j];
            }
            __syncthreads();
#pragma unroll
            for (int kk = 0; kk < 32; kk++) {
                ull wp0 = *(const ull*)&W_s[kk][j0];
                ull wp1 = *(const ull*)&W_s[kk][j0 + 2];
#pragma unroll
                for (int i = 0; i < 4; i++) {
                    ull ad = A2[(b0 + i) * 34 + kk];
                    ffma2(accp[i][0], ad, wp0);
                    ffma2(accp[i][1], ad, wp1);
                }
            }
            __syncthreads();
        }
    }
#pragma unroll
    for (int i = 0; i < 4; i++) {
#pragma unroll
        for (int jp = 0; jp < 2; jp++) {
            float2 f = fupk(accp[i][jp]);
            int j = jbase + j0 + jp * 2;
            float v0 = f.x, v1 = f.y;
            if (ks == 0 && jb < 32) { v0 += bias[j]; v1 += bias[j + 1]; }
            g_zp[((ks * 32) + (b0 + i)) * 5120 + j]     = v0;
            g_zp[((ks * 32) + (b0 + i)) * 5120 + j + 1] = v1;
        }
    }
}

// ---------------- K2: reduce partials, activations, h, c, h^2 partials ----------------
__global__ __launch_bounds__(256) void k_gates(const float* __restrict__ c_tm1,
                                               float* __restrict__ out)
{
    int blk = blockIdx.x;            // 128
    int b = blk >> 2, uc = blk & 3;
    int u = uc * 256 + threadIdx.x;
    float zi = 0, zf = 0, zc = 0, zo = 0, ri = 0;
#pragma unroll
    for (int s = 0; s < 4; s++) {
        const float* p = &g_zp[(s * 32 + b) * 5120];
        zi += p[u]; zf += p[1024 + u]; zc += p[2048 + u]; zo += p[3072 + u]; ri += p[4096 + u];
    }
    float ig = hsig(zi + ri), fg = hsig(zf), og = hsig(zo);
    float c = fg * c_tm1[b * 1024 + u] + ig * tanhf(zc);
    float hh = og * tanhf(c);
    out[C_OFF + b * 1024 + u] = c;
    out[H_OFF + b * 1024 + u] = hh;
    g_h[b * 1024 + u] = hh;

    __shared__ float red[256];
    red[threadIdx.x] = hh * hh;
    __syncthreads();
    for (int s = 128; s > 0; s >>= 1) {
        if (threadIdx.x < s) red[threadIdx.x] += red[threadIdx.x + s];
        __syncthreads();
    }
    if (threadIdx.x == 0) g_hss[blk] = red[0];
}

__global__ void k_hinv() {
    int b = threadIdx.x;
    if (b < 32) {
        float s = g_hss[b * 4] + g_hss[b * 4 + 1] + g_hss[b * 4 + 2] + g_hss[b * 4 + 3];
        g_hinv[b] = rsqrtf(fmaxf(s, 1e-12f));
    }
}

// ---------------- K4: fused membank pass (dots + ss + mem_new), f32x2 + LDS.128 ------
// grid 1024 blocks (64 m rows each), 256 threads, dynamic smem 70656 B.
// layout: ww2 (ull[32*66]) | h_s (float[32*140]) | mb_s (float[64*140])
#define K4_SMEM (32*66*8 + 32*140*4 + 64*140*4)

__global__ __launch_bounds__(256, 2) void k_sim_mem(const float* __restrict__ mb,
                                                    const float* __restrict__ wr_prev,
                                                    const float* __restrict__ wlu,
                                                    const float* __restrict__ wg,
                                                    float* __restrict__ out)
{
    extern __shared__ __align__(16) char smem_raw[];
    ull*   ww2  = (ull*)smem_raw;                                  // [32][66] dup-packed
    float* h_s  = (float*)(smem_raw + 32 * 66 * 8);                // [32][140]
    float* mb_s = (float*)(smem_raw + 32 * 66 * 8 + 32 * 140 * 4); // [64][140]
    float* red    = mb_s;                                          // alias (epilogue)
    float* ss_red = mb_s + 128 * 17;

    int m0 = blockIdx.x * 64;
    int t = threadIdx.x;

    // ww2 fill (dup-packed)
    float sg = 1.0f / (1.0f + expf(-wg[0]));
#pragma unroll
    for (int i = 0; i < 8; i++) {
        int e = t + i * 256;
        int b = e >> 6, m = e & 63;
        size_t gi = (size_t)b * 65536 + m0 + m;
        ww2[b * 66 + m] = fdup(sg * wr_prev[gi] + (1.0f - sg) * wlu[gi]);
    }

    int tl = t & 127, us = t >> 7;
    int bg = tl & 7, mg = tl >> 3;      // dots: b rows bg+{0,8,16,24}, m rows mg+{0,16,32,48}
    int ugn = t & 15, mgn = t >> 4;     // memnew: m rows mgn*4+{0..3}, u cols ugn*8+{0..7}

    ull dotp[4][4];
    ull ssp[4];
#pragma unroll
    for (int i = 0; i < 4; i++) {
#pragma unroll
        for (int j = 0; j < 4; j++) dotp[i][j] = 0ULL;
        ssp[i] = 0ULL;
    }

    for (int uc = 0; uc < 1024; uc += 128) {
        __syncthreads();
        // fill h_s [32][128]
#pragma unroll
        for (int i = 0; i < 4; i++) {
            int f = t + i * 256;
            int row = f >> 5, c = (f & 31) * 4;
            *(float4*)&h_s[row * 140 + c] = *(const float4*)&g_h[row * 1024 + uc + c];
        }
        // fill mb_s [64][128]
#pragma unroll
        for (int i = 0; i < 8; i++) {
            int f = t + i * 256;
            int row = f >> 5, c = (f & 31) * 4;
            *(float4*)&mb_s[row * 140 + c] =
                *(const float4*)&mb[(size_t)(m0 + row) * 1024 + uc + c];
        }
        __syncthreads();

        // ---- dots: each thread 4b x 4m, its u-half (16 of 32 u4-steps) ----
#pragma unroll 4
        for (int u4 = us * 16; u4 < us * 16 + 16; u4++) {
            ulonglong2 hp[4], mp[4];
#pragma unroll
            for (int bi = 0; bi < 4; bi++)
                hp[bi] = *(const ulonglong2*)&h_s[(bg + bi * 8) * 140 + u4 * 4];
#pragma unroll
            for (int mi = 0; mi < 4; mi++)
                mp[mi] = *(const ulonglong2*)&mb_s[(mg + mi * 16) * 140 + u4 * 4];
#pragma unroll
            for (int bi = 0; bi < 4; bi++)
#pragma unroll
                for (int mi = 0; mi < 4; mi++) {
                    ffma2(dotp[bi][mi], hp[bi].x, mp[mi].x);
                    ffma2(dotp[bi][mi], hp[bi].y, mp[mi].y);
                }
            if (bg == 0) {
#pragma unroll
                for (int mi = 0; mi < 4; mi++) {
                    ffma2(ssp[mi], mp[mi].x, mp[mi].x);
                    ffma2(ssp[mi], mp[mi].y, mp[mi].y);
                }
            }
        }

        // ---- mem_new: each thread 4m x 8u ----
        ull acc[4][4];
#pragma unroll
        for (int mi = 0; mi < 4; mi++) {
            int m = mgn * 4 + mi;
            ulonglong2 a0 = *(const ulonglong2*)&mb_s[m * 140 + ugn * 8];
            ulonglong2 a1 = *(const ulonglong2*)&mb_s[m * 140 + ugn * 8 + 4];
            acc[mi][0] = a0.x; acc[mi][1] = a0.y; acc[mi][2] = a1.x; acc[mi][3] = a1.y;
        }
#pragma unroll 4
        for (int b = 0; b < 32; b++) {
            ulonglong2 w01 = *(const ulonglong2*)&ww2[b * 66 + mgn * 4];
            ulonglong2 w23 = *(const ulonglong2*)&ww2[b * 66 + mgn * 4 + 2];
            ulonglong2 h0 = *(const ulonglong2*)&h_s[b * 140 + ugn * 8];
            ulonglong2 h1 = *(const ulonglong2*)&h_s[b * 140 + ugn * 8 + 4];
            ffma2(acc[0][0], w01.x, h0.x); ffma2(acc[0][1], w01.x, h0.y);
            ffma2(acc[0][2], w01.x, h1.x); ffma2(acc[0][3], w01.x, h1.y);
            ffma2(acc[1][0], w01.y, h0.x); ffma2(acc[1][1], w01.y, h0.y);
            ffma2(acc[1][2], w01.y, h1.x); ffma2(acc[1][3], w01.y, h1.y);
            ffma2(acc[2][0], w23.x, h0.x); ffma2(acc[2][1], w23.x, h0.y);
            ffma2(acc[2][2], w23.x, h1.x); ffma2(acc[2][3], w23.x, h1.y);
            ffma2(acc[3][0], w23.y, h0.x); ffma2(acc[3][1], w23.y, h0.y);
            ffma2(acc[3][2], w23.y, h1.x); ffma2(acc[3][3], w23.y, h1.y);
        }
#pragma unroll
        for (int mi = 0; mi < 4; mi++) {
            size_t o = MEM_OFF + (size_t)(m0 + mgn * 4 + mi) * 1024 + uc + ugn * 8;
            ulonglong2 s0; s0.x = acc[mi][0]; s0.y = acc[mi][1];
            ulonglong2 s1; s1.x = acc[mi][2]; s1.y = acc[mi][3];
            *(ulonglong2*)&out[o]     = s0;
            *(ulonglong2*)&out[o + 4] = s1;
        }
    }

    // ---- epilogue: combine u-halves, normalize, store sim ----
    __syncthreads();
    float dsum[16], ssv[4];
#pragma unroll
    for (int bi = 0; bi < 4; bi++)
#pragma unroll
        for (int mi = 0; mi < 4; mi++) {
            float2 f = fupk(dotp[bi][mi]);
            dsum[bi * 4 + mi] = f.x + f.y;
        }
#pragma unroll
    for (int mi = 0; mi < 4; mi++) {
        float2 f = fupk(ssp[mi]);
        ssv[mi] = f.x + f.y;
    }
    if (us == 1) {
#pragma unroll
        for (int k = 0; k < 16; k++) red[tl * 17 + k] = dsum[k];
        if (bg == 0) {
#pragma unroll
            for (int mi = 0; mi < 4; mi++) ss_red[mg + mi * 16] = ssv[mi];
        }
    }
    __syncthreads();
    if (us == 0) {
#pragma unroll
        for (int k = 0; k < 16; k++) dsum[k] += red[tl * 17 + k];
        if (bg == 0) {
#pragma unroll
            for (int mi = 0; mi < 4; mi++) {
                float s = ss_red[mg + mi * 16] + ssv[mi];
                ss_red[mg + mi * 16] = rsqrtf(fmaxf(s, 1e-12f));
            }
        }
    }
    __syncthreads();
    if (us == 0) {
#pragma unroll
        for (int bi = 0; bi < 4; bi++) {
            int b = bg + bi * 8;
            float hinv = g_hinv[b];
#pragma unroll
            for (int mi = 0; mi < 4; mi++) {
                int m = mg + mi * 16;
                out[WR_OFF + (size_t)b * 65536 + m0 + m] = dsum[bi * 4 + mi] * hinv * ss_red[m];
            }
        }
    }
}

// ---------------- K5: softmax partial reductions ----------------
__global__ __launch_bounds__(256) void k_red1(const float* __restrict__ outr)
{
    int blk = blockIdx.x;             // 512 = 32 b x 16 partitions
    int b = blk >> 4, p = blk & 15;
    const float* s = outr + WR_OFF + (size_t)b * 65536 + p * 4096;
    int t = threadIdx.x;
    float mx = -FLT_MAX;
    for (int k = 0; k < 16; k++) mx = fmaxf(mx, s[k * 256 + t]);
    __shared__ float red[256];
    red[t] = mx; __syncthreads();
    for (int st = 128; st > 0; st >>= 1) {
        if (t < st) red[t] = fmaxf(red[t], red[t + st]);
        __syncthreads();
    }
    float bmax = red[0];
    __syncthreads();
    float sum = 0;
    for (int k = 0; k < 16; k++) sum += expf(s[k * 256 + t] - bmax);
    red[t] = sum; __syncthreads();
    for (int st = 128; st > 0; st >>= 1) {
        if (t < st) red[t] += red[t + st];
        __syncthreads();
    }
    if (t == 0) { g_pm[blk] = bmax; g_ps[blk] = red[0]; }
}

__global__ void k_red2()
{
    int b = threadIdx.x;
    if (b >= 32) return;
    float gm = -FLT_MAX;
    for (int p = 0; p < 16; p++) gm = fmaxf(gm, g_pm[b * 16 + p]);
    float den = 0;
    for (int p = 0; p < 16; p++) den += g_ps[b * 16 + p] * expf(g_pm[b * 16 + p] - gm);
    g_gmax[b] = gm;
    g_invden[b] = 1.0f / den;
}

// ---------------- K6: wr (in place over sim), wu_new, order-stat partials ----------------
__global__ __launch_bounds__(256) void k_wr_wu(const float* __restrict__ wu,
                                               const float* __restrict__ wlu,
                                               const float* __restrict__ wr_prev,
                                               const float* __restrict__ wg,
                                               float* __restrict__ out)
{
    int blk = blockIdx.x;             // 1024 = 32 b x 32 chunks
    int b = blk >> 5, mc = blk & 31;
    int t = threadIdx.x;
    size_t base = (size_t)b * 65536 + (size_t)mc * 2048 + (size_t)t * 8;
    float sg = 1.0f / (1.0f + expf(-wg[0]));
    float gm = g_gmax[b], inv = g_invden[b];

    float s1 = FLT_MAX, s2 = FLT_MAX;
    float mv = FLT_MAX; int mi_ = 0x7fffffff;
#pragma unroll
    for (int k = 0; k < 8; k++) {
        size_t idx = base + k;
        float sim = out[WR_OFF + idx];
        float wr = expf(sim - gm) * inv;
        out[WR_OFF + idx] = wr;
        float ww = sg * wr_prev[idx] + (1.0f - sg) * wlu[idx];
        float wun = 0.5f * wu[idx] + wr + ww;
        out[WU_OFF + idx] = wun;
        if (wun < s1) { s2 = s1; s1 = wun; }
        else if (wun < s2) { s2 = wun; }
        int m = (int)(idx - (size_t)b * 65536);
        if (wun < mv || (wun == mv && m < mi_)) { mv = wun; mi_ = m; }
    }
    __shared__ float r1[256], r2[256], rv[256];
    __shared__ int ri_[256];
    r1[t] = s1; r2[t] = s2; rv[t] = mv; ri_[t] = mi_;
    __syncthreads();
    for (int st = 128; st > 0; st >>= 1) {
        if (t < st) {
            float b1 = r1[t + st], b2 = r2[t + st];
            float a1 = r1[t], a2 = r2[t];
            if (b1 < a1) { a2 = fminf(a1, b2); a1 = b1; }
            else         { a2 = fminf(a2, b1); }
            r1[t] = a1; r2[t] = a2;
            float bv = rv[t + st]; int bi2 = ri_[t + st];
            if (bv < rv[t] || (bv == rv[t] && bi2 < ri_[t])) { rv[t] = bv; ri_[t] = bi2; }
        }
        __syncthreads();
    }
    if (t == 0) { g_bv1[blk] = r1[0]; g_bv2[blk] = r2[0]; g_bmv[blk] = rv[0]; g_bmi[blk] = ri_[0]; }
}

__global__ void k_redmin()
{
    int b = threadIdx.x;
    __shared__ int sidx[32];
    if (b < 32) {
        float s1 = FLT_MAX, s2 = FLT_MAX;
        float mv = FLT_MAX; int mi_ = 0x7fffffff;
        for (int p = 0; p < 32; p++) {
            int blk = b * 32 + p;
            float b1 = g_bv1[blk], b2 = g_bv2[blk];
            if (b1 < s1) { s2 = fminf(s1, b2); s1 = b1; }
            else         { s2 = fminf(s2, b1); }
            float bv = g_bmv[blk]; int bi2 = g_bmi[blk];
            if (bv < mv || (bv == mv && bi2 < mi_)) { mv = bv; mi_ = bi2; }
        }
        g_nth[b] = s2;
        sidx[b] = mi_;
    }
    __syncthreads();
    if (b == 0) {
        int m = sidx[0];
        for (int i = 1; i < 32; i++) m = min(m, sidx[i]);
        g_si[0] = m;
    }
}

// ---------------- K7: wlu_new ----------------
__global__ __launch_bounds__(256) void k_wlu(float* __restrict__ out)
{
    int blk = blockIdx.x;
    int b = blk >> 5, mc = blk & 31;
    size_t base = (size_t)b * 65536 + (size_t)mc * 2048 + (size_t)threadIdx.x * 8;
    float nth = g_nth[b];
#pragma unroll
    for (int k = 0; k < 8; k++)
        out[WLU_OFF + base + k] = (out[WU_OFF + base + k] <= nth) ? 1.0f : 0.0f;
}

// ---------------- K8: keep-row fixup on mem_new ----------------
__global__ void k_fixrow(const float* __restrict__ mb, float* __restrict__ out)
{
    int m = g_si[0];
    for (int u = threadIdx.x; u < 1024; u += blockDim.x)
        out[MEM_OFF + (size_t)m * 1024 + u] -= mb[(size_t)m * 1024 + u];
}

// ---------------- K9: r = wr @ membank (split-K), f32x2 packed over b-pairs -------------
__global__ __launch_bounds__(256) void k_r(const float* __restrict__ mb,
                                           const float* __restrict__ out)
{
    __shared__ __align__(16) float wr_t[64][36];
    int slice = blockIdx.x >> 2;
    int ut = blockIdx.x & 3;
    int t = threadIdx.x;
    int tu = t & 63;
    int b0 = (t >> 6) * 8;
    int u = ut * 256 + tu * 4;
    int mbase = slice * 512;

    ull accp[4][4];
#pragma unroll
    for (int i = 0; i < 4; i++)
#pragma unroll
        for (int j = 0; j < 4; j++) accp[i][j] = 0ULL;

    for (int mc = 0; mc < 512; mc += 64) {
#pragma unroll
        for (int i = 0; i < 8; i++) {
            int e = t + i * 256;
            int b = e >> 6, mm = e & 63;
            wr_t[mm][b] = out[WR_OFF + (size_t)b * 65536 + mbase + mc + mm];
        }
        __syncthreads();
#pragma unroll 8
        for (int mm = 0; mm < 64; mm++) {
            float4 v = *(const float4*)&mb[(size_t)(mbase + mc + mm) * 1024 + u];
            ull vd0 = fdup(v.x), vd1 = fdup(v.y), vd2 = fdup(v.z), vd3 = fdup(v.w);
            ulonglong2 w01 = *(const ulonglong2*)&wr_t[mm][b0];
            ulonglong2 w23 = *(const ulonglong2*)&wr_t[mm][b0 + 4];
            ffma2(accp[0][0], w01.x, vd0); ffma2(accp[0][1], w01.x, vd1);
            ffma2(accp[0][2], w01.x, vd2); ffma2(accp[0][3], w01.x, vd3);
            ffma2(accp[1][0], w01.y, vd0); ffma2(accp[1][1], w01.y, vd1);
            ffma2(accp[1][2], w01.y, vd2); ffma2(accp[1][3], w01.y, vd3);
            ffma2(accp[2][0], w23.x, vd0); ffma2(accp[2][1], w23.x, vd1);
            ffma2(accp[2][2], w23.x, vd2); ffma2(accp[2][3], w23.x, vd3);
            ffma2(accp[3][0], w23.y, vd0); ffma2(accp[3][1], w23.y, vd1);
            ffma2(accp[3][2], w23.y, vd2); ffma2(accp[3][3], w23.y, vd3);
        }
        __syncthreads();
    }
#pragma unroll
    for (int bp = 0; bp < 4; bp++) {
        float2 f0 = fupk(accp[bp][0]), f1 = fupk(accp[bp][1]);
        float2 f2 = fupk(accp[bp][2]), f3 = fupk(accp[bp][3]);
        size_t base = ((size_t)slice * 32 + b0 + bp * 2) * 1024 + u;
        *(float4*)&g_rp[base]        = make_float4(f0.x, f1.x, f2.x, f3.x);
        *(float4*)&g_rp[base + 1024] = make_float4(f0.y, f1.y, f2.y, f3.y);
    }
}

__global__ __launch_bounds__(256) void k_rred(float* __restrict__ out)
{
    int idx = blockIdx.x * 256 + threadIdx.x;   // 0..32767
    float s = 0;
    for (int sl = 0; sl < 128; sl++) s += g_rp[(size_t)sl * 32768 + idx];
    out[R_OFF + idx] = s;
}

// ---------------- launcher ----------------
extern "C" void kernel_launch(void* const* d_in, const int* in_sizes, int n_in,
                              void* d_out, int out_size)
{
    const float* x        = (const float*)d_in[0];
    const float* h_tm1    = (const float*)d_in[1];
    const float* c_tm1    = (const float*)d_in[2];
    const float* r_tm1    = (const float*)d_in[3];
    const float* membank  = (const float*)d_in[4];
    const float* wu       = (const float*)d_in[5];
    const float* wlu      = (const float*)d_in[6];
    const float* wr_prev  = (const float*)d_in[7];
    const float* Wk       = (const float*)d_in[8];
    const float* RK       = (const float*)d_in[9];
    const float* bias     = (const float*)d_in[10];
    const float* wgate    = (const float*)d_in[11];
    float* out = (float*)d_out;

    cudaFuncSetAttribute(k_sim_mem, cudaFuncAttributeMaxDynamicSharedMemorySize, K4_SMEM);

    k_gemm<<<160, 256>>>(x, h_tm1, r_tm1, Wk, RK, bias);
    k_gates<<<128, 256>>>(c_tm1, out);
    k_hinv<<<1, 32>>>();
    k_sim_mem<<<1024, 256, K4_SMEM>>>(membank, wr_prev, wlu, wgate, out);
    k_red1<<<512, 256>>>(out);
    k_red2<<<1, 32>>>();
    k_wr_wu<<<1024, 256>>>(wu, wlu, wr_prev, wgate, out);
    k_redmin<<<1, 32>>>();
    k_wlu<<<1024, 256>>>(out);
    k_fixrow<<<1, 256>>>(membank, out);
    k_r<<<512, 256>>>(membank, out);
    k_rred<<<128, 256>>>(out);
}